// round 16
// baseline (speedup 1.0000x reference)
#include <cuda_runtime.h>
#include <cuda_fp16.h>
#include <cstdint>
#include <cstddef>

// Problem constants
#define DIMN 2_56_
#undef DIMN 
#define DIMN 256
#define KTOK 2048
#define BSZ  256
#define NSM  148
#define TILES 4096   // 2048 k-tokens x 2 b-halves

// ---------------- device globals (scratch; no allocs allowed) ----------------
__device__ __align__(16) float   g_qq[BSZ * DIMN];   // query@Wq^T + bq + bref
__device__ __align__(16) __half  g_W16[DIMN * DIMN]; // Wref rounded to fp16

// ---------------- helpers ----------------
__device__ __forceinline__ uint32_t smem_u32(const void* p) {
    return (uint32_t)__cvta_generic_to_shared(p);
}

__device__ __forceinline__ uint32_t swz(uint32_t o) {
    return o ^ ((o >> 3) & 0x70);
}

__device__ __forceinline__ uint32_t pack2h(__half a, __half b) {
    __half2 t(a, b);  // a at low half
    return *reinterpret_cast<uint32_t*>(&t);
}

__device__ __forceinline__ float tanha(float x) {
    float y;
    asm("tanh.approx.f32 %0, %1;" : "=f"(y) : "f"(x));
    return y;
}

__device__ __forceinline__ void ldsm4(uint32_t* r, uint32_t addr) {
    asm volatile("ldmatrix.sync.aligned.m8n8.x4.shared.b16 {%0,%1,%2,%3}, [%4];"
                 : "=r"(r[0]), "=r"(r[1]), "=r"(r[2]), "=r"(r[3])
                 : "r"(addr));
}

__device__ __forceinline__ void mma_f16(float* c, const uint32_t* a,
                                        uint32_t b0, uint32_t b1) {
    asm volatile(
        "mma.sync.aligned.m16n8k16.row.col.f32.f16.f16.f32 "
        "{%0,%1,%2,%3}, {%4,%5,%6,%7}, {%8,%9}, {%0,%1,%2,%3};"
        : "+f"(c[0]), "+f"(c[1]), "+f"(c[2]), "+f"(c[3])
        : "r"(a[0]), "r"(a[1]), "r"(a[2]), "r"(a[3]), "r"(b0), "r"(b1));
}

__device__ __forceinline__ void cp_async16(uint32_t dst, const void* src) {
    asm volatile("cp.async.cg.shared.global [%0], [%1], 16;"
                 :: "r"(dst), "l"(src) : "memory");
}

__device__ __forceinline__ void prefetch_l1(const void* p) {
    asm volatile("prefetch.global.L1 [%0];" :: "l"(p));
}

// ---------------- merged prep kernel (unchanged from R14) ----------------
__global__ void prep_all(const float* __restrict__ query,
                         const float* __restrict__ Wq,
                         const float* __restrict__ bq,
                         const float* __restrict__ bref,
                         const float* __restrict__ Wref) {
    const int tid = threadIdx.x;
    if (blockIdx.x >= 64) {
        int i = (blockIdx.x - 64) * 2048 + tid;
#pragma unroll
        for (int j = 0; j < 8; j++)
            g_W16[i + j * 256] = __float2half(Wref[i + j * 256]);
        return;
    }
    __shared__ __align__(16) float qrows[4 * DIMN];
    const int bq0 = blockIdx.x * 4;
#pragma unroll
    for (int r = 0; r < 4; r++)
        qrows[r * DIMN + tid] = query[(bq0 + r) * DIMN + tid];
    __syncthreads();
    const float4* w  = (const float4*)(Wq + (size_t)tid * DIMN);
    const float4* a0 = (const float4*)(qrows);
    const float4* a1 = (const float4*)(qrows + DIMN);
    const float4* a2 = (const float4*)(qrows + 2 * DIMN);
    const float4* a3 = (const float4*)(qrows + 3 * DIMN);
    float s0 = 0.f, s1 = 0.f, s2 = 0.f, s3 = 0.f;
#pragma unroll 8
    for (int e = 0; e < 64; e++) {
        float4 wv = w[e];
        float4 x0 = a0[e], x1 = a1[e], x2 = a2[e], x3 = a3[e];
        s0 = fmaf(wv.x, x0.x, fmaf(wv.y, x0.y, fmaf(wv.z, x0.z, fmaf(wv.w, x0.w, s0))));
        s1 = fmaf(wv.x, x1.x, fmaf(wv.y, x1.y, fmaf(wv.z, x1.z, fmaf(wv.w, x1.w, s1))));
        s2 = fmaf(wv.x, x2.x, fmaf(wv.y, x2.y, fmaf(wv.z, x2.z, fmaf(wv.w, x2.w, s2))));
        s3 = fmaf(wv.x, x3.x, fmaf(wv.y, x3.y, fmaf(wv.z, x3.z, fmaf(wv.w, x3.w, s3))));
    }
    const float bb = bq[tid] + bref[tid];
    g_qq[(bq0 + 0) * DIMN + tid] = s0 + bb;
    g_qq[(bq0 + 1) * DIMN + tid] = s1 + bb;
    g_qq[(bq0 + 2) * DIMN + tid] = s2 + bb;
    g_qq[(bq0 + 3) * DIMN + tid] = s3 + bb;
}

// ---------------- main kernel: persistent CTAs, W fully smem-resident ----------------
// Grid 148, 512 threads, 1 CTA/SM. Tile tt = k*2 + bhalf; CTA processes
// tt = bid, bid+148, ...  Each tile: 128 b-rows x N=256, K streamed in 4 chunks.
// SMEM (224KB):
//   W:     4 chunks x 32768 (256 d-rows x 128B, SW128)      [0, 131072)
//   A16:   2 bufs  x 16384 (128 rows x 128B fp16, SW128)    [131072, 163840)
//   STAGE: 2 bufs  x 32768 (128 rows x 64 fp32, linear)     [163840, 229376)
//   red (2KB) reuses the idle A16 buffer during the fold.
#define SM_A16   131072
#define SM_STAGE 163840
#define SMEM_TOTAL 229376

__global__ void __launch_bounds__(512, 1) attn_main(const float* __restrict__ enc,
                                                    const float* __restrict__ vvec,
                                                    float* __restrict__ out) {
    extern __shared__ char smem[];
    const uint32_t sb = smem_u32(smem);
    const int tid = threadIdx.x;
    const int wid = tid >> 5;
    const int lane = tid & 31;
    const int wm = wid & 3;            // M block: rows wm*32 .. +32 (of 128)
    const int wn = wid >> 2;           // N slice: cols wn*64 .. +64 (of 256)
    const int bid = blockIdx.x;

    // per-lane swizzled ldmatrix bases
    const uint32_t a0 = swz((uint32_t)((wm * 32 + (lane & 15)) * 128 + (lane >> 4) * 16));
    const uint32_t a1 = a0 + 2048;  // +16 rows (additive above swizzle bits)
    const uint32_t w_row = (uint32_t)((lane & 7) + ((lane & 16) ? 8 : 0));
    const uint32_t w0s = swz((uint32_t)((wn * 64 + w_row) * 128 + ((lane >> 3) & 1) * 16));

    const int q = lane >> 2;
    const int cbase = 2 * (lane & 3);

    // preload v fragment (constant across tiles) into registers
    float2 vv[8];
#pragma unroll
    for (int t = 0; t < 8; t++)
        vv[t] = *(const float2*)(vvec + wn * 64 + t * 8 + cbase);

    // ---- load full W into smem (once): 4 chunks, 16 granules/thread, 1 group ----
#pragma unroll
    for (int c = 0; c < 4; c++) {
#pragma unroll
        for (int j = 0; j < 4; j++) {
            int gi = j * 512 + tid;           // 2048 granules of 16B per chunk
            int d = gi >> 3, seg = gi & 7;
            cp_async16(sb + (uint32_t)c * 32768 + swz((uint32_t)(d * 128 + seg * 16)),
                       g_W16 + d * DIMN + c * 64 + seg * 8);
        }
    }
    asm volatile("cp.async.commit_group;" ::: "memory");

    // number of pipeline steps for this CTA
    const int ntiles = (TILES - bid + NSM - 1) / NSM;
    const int G = 4 * ntiles;

    // A chunk stage issue for (tile, chunk) into staging buffer buf
    auto issue_stage = [&](int tile, int c, int buf) {
        const int kb2 = (tile >> 1) * BSZ + (tile & 1) * 128;
#pragma unroll
        for (int j = 0; j < 4; j++) {
            int gi = j * 512 + tid;           // 2048 granules of 16B
            int m = gi >> 4, f4 = gi & 15;
            cp_async16(sb + SM_STAGE + (uint32_t)buf * 32768 + (uint32_t)gi * 16,
                       enc + (size_t)(kb2 + m) * DIMN + c * 64 + f4 * 4);
        }
        asm volatile("cp.async.commit_group;" ::: "memory");
    };

    // convert staging buf -> A16 buf (thread reads only its own granules,
    // so the later issue_stage into the same granules is in-thread ordered)
    auto convert = [&](int buf) {
        char* dst = (char*)smem + SM_A16 + (size_t)buf * 16384;
        const char* src = (char*)smem + SM_STAGE + (size_t)buf * 32768;
#pragma unroll
        for (int j = 0; j < 4; j++) {
            int gi = j * 512 + tid;
            int m = gi >> 4, f4 = gi & 15;
            float4 x = *(const float4*)(src + (size_t)gi * 16);
            __half h0 = __float2half(x.x), h1 = __float2half(x.y);
            __half h2 = __float2half(x.z), h3 = __float2half(x.w);
            *(uint2*)(dst + swz((uint32_t)(m * 128 + f4 * 8))) =
                make_uint2(pack2h(h0, h1), pack2h(h2, h3));
        }
    };

    // prologue: stages for steps 0 and 1 (tile bid, chunks 0 and 1)
    issue_stage(bid, 0, 0);
    issue_stage(bid, 1, 1);

    // accumulators: 2 m-tiles x 8 n8-tiles x 4 regs
    float acc[2][8][4];
#pragma unroll
    for (int mt = 0; mt < 2; mt++)
#pragma unroll
        for (int t = 0; t < 8; t++)
#pragma unroll
            for (int j = 0; j < 4; j++) acc[mt][t][j] = 0.0f;

    int g = 0;
    for (int tt = bid; tt < TILES; tt += NSM) {
        const int k = tt >> 1;
        const int b0 = (tt & 1) * 128;
        const int rbase = b0 + wm * 32 + q;
        const float* qp0 = g_qq + (size_t)rbase * DIMN;
        const float* qp1 = g_qq + (size_t)(rbase + 8) * DIMN;
        const float* qp2 = g_qq + (size_t)(rbase + 16) * DIMN;
        const float* qp3 = g_qq + (size_t)(rbase + 24) * DIMN;

        for (int c = 0; c < 4; c++, g++) {
            const int buf = g & 1;
            const uint32_t abase = sb + SM_A16 + (uint32_t)buf * 16384;
            const uint32_t wbase = sb + (uint32_t)c * 32768;

            // stage(g) complete; stage(g+1) may remain in flight
            if (g < G - 1) {
                asm volatile("cp.async.wait_group 1;" ::: "memory");
            } else {
                asm volatile("cp.async.wait_group 0;" ::: "memory");
            }
            __syncthreads();   // compute(g-1) done -> A16[buf] is rewritable

            convert(buf);
            if (g + 2 < G) {
                const int tile2 = tt + ((c + 2) >> 2) * NSM;
                issue_stage(tile2, (c + 2) & 3, buf);
            }
            if (c == 2) {
                // prefetch qq lines for the fold after chunk 3
                const int cb0 = wn * 64;
#pragma unroll
                for (int h = 0; h < 2; h++) {
                    prefetch_l1(qp0 + cb0 + h * 32);
                    prefetch_l1(qp1 + cb0 + h * 32);
                    prefetch_l1(qp2 + cb0 + h * 32);
                    prefetch_l1(qp3 + cb0 + h * 32);
                }
            }
            __syncthreads();   // A16[buf] visible

            // ---- compute chunk: 4 kk x 4 np x 4 MMA ----
#pragma unroll
            for (int kk = 0; kk < 4; kk++) {
                const uint32_t kx = (uint32_t)(kk * 32);
                uint32_t aF0[4], aF1[4];
                ldsm4(aF0, abase + (a0 ^ kx));
                ldsm4(aF1, abase + (a1 ^ kx));
                const uint32_t wk = w0s ^ kx;
#pragma unroll
                for (int np = 0; np < 4; np++) {
                    uint32_t w[4];
                    ldsm4(w, wbase + wk + np * 2048);
                    mma_f16(acc[0][2 * np],     aF0, w[0], w[1]);
                    mma_f16(acc[0][2 * np + 1], aF0, w[2], w[3]);
                    mma_f16(acc[1][2 * np],     aF1, w[0], w[1]);
                    mma_f16(acc[1][2 * np + 1], aF1, w[2], w[3]);
                }
            }
        }

        // ---- fold: u[r] = sum_d v[d]*tanh(C[r,d]+qq[r,d]) over warp's 64 cols ----
        float u00 = 0.f, u01 = 0.f, u10 = 0.f, u11 = 0.f;
#pragma unroll
        for (int t = 0; t < 8; t++) {
            int cb = wn * 64 + t * 8 + cbase;
            float2 qa = *(const float2*)(qp0 + cb);
            float2 qb = *(const float2*)(qp1 + cb);
            float2 qc = *(const float2*)(qp2 + cb);
            float2 qd = *(const float2*)(qp3 + cb);
            u00 = fmaf(vv[t].x, tanha(acc[0][t][0] + qa.x), u00);
            u00 = fmaf(vv[t].y, tanha(acc[0][t][1] + qa.y), u00);
            u01 = fmaf(vv[t].x, tanha(acc[0][t][2] + qb.x), u01);
            u01 = fmaf(vv[t].y, tanha(acc[0][t][3] + qb.y), u01);
            u10 = fmaf(vv[t].x, tanha(acc[1][t][0] + qc.x), u10);
            u10 = fmaf(vv[t].y, tanha(acc[1][t][1] + qc.y), u10);
            u11 = fmaf(vv[t].x, tanha(acc[1][t][2] + qd.x), u11);
            u11 = fmaf(vv[t].y, tanha(acc[1][t][3] + qd.y), u11);
#pragma unroll
            for (int mt = 0; mt < 2; mt++)
#pragma unroll
                for (int j = 0; j < 4; j++) acc[mt][t][j] = 0.0f;
        }
        u00 += __shfl_xor_sync(0xFFFFFFFF, u00, 1);
        u00 += __shfl_xor_sync(0xFFFFFFFF, u00, 2);
        u01 += __shfl_xor_sync(0xFFFFFFFF, u01, 1);
        u01 += __shfl_xor_sync(0xFFFFFFFF, u01, 2);
        u10 += __shfl_xor_sync(0xFFFFFFFF, u10, 1);
        u10 += __shfl_xor_sync(0xFFFFFFFF, u10, 2);
        u11 += __shfl_xor_sync(0xFFFFFFFF, u11, 1);
        u11 += __shfl_xor_sync(0xFFFFFFFF, u11, 2);

        // cross-warp (wn) reduction; red lives in the idle A16 buffer
        // (A16[g&1]: its convert happens only after the next iteration's
        //  first sync, so reads below are safe)
        float* red = (float*)(smem + SM_A16 + (size_t)(g & 1) * 16384);
        __syncthreads();   // compute done; idle A16 buffer reusable
        if ((lane & 3) == 0) {
            red[wn * 128 + wm * 32 + q] = u00;
            red[wn * 128 + wm * 32 + 8 + q] = u01;
            red[wn * 128 + wm * 32 + 16 + q] = u10;
            red[wn * 128 + wm * 32 + 24 + q] = u11;
        }
        __syncthreads();
        if (tid < 128) {
            float u = (red[tid] + red[128 + tid]) + (red[256 + tid] + red[384 + tid]);
            out[(size_t)(b0 + tid) * KTOK + k] = 10.0f * tanhf(u);
        }
    }
}

// ---------------- launch ----------------
extern "C" void kernel_launch(void* const* d_in, const int* in_sizes, int n_in,
                              void* d_out, int out_size) {
    (void)in_sizes; (void)n_in; (void)out_size;
    const float* enc   = (const float*)d_in[0];
    const float* query = (const float*)d_in[1];
    const float* Wq    = (const float*)d_in[2];
    const float* bq    = (const float*)d_in[3];
    const float* Wref  = (const float*)d_in[4];
    const float* bref  = (const float*)d_in[5];
    const float* v     = (const float*)d_in[6];
    float* out = (float*)d_out;

    prep_all<<<96, 256>>>(query, Wq, bq, bref, Wref);

    cudaFuncSetAttribute(attn_main, cudaFuncAttributeMaxDynamicSharedMemorySize,
                         SMEM_TOTAL);
    attn_main<<<NSM, 512, SMEM_TOTAL>>>(enc, v, out);
}

// round 17
// speedup vs baseline: 1.1111x; 1.1111x over previous
#include <cuda_runtime.h>
#include <cuda_fp16.h>
#include <cstdint>
#include <cstddef>

// Problem constants
#define DIMN 256
#define KTOK 2048
#define BSZ  256

// ---------------- device globals (scratch; no allocs allowed) ----------------
__device__ __align__(16) float   g_qq[BSZ * DIMN];   // query@Wq^T + bq + bref
__device__ __align__(16) __half  g_W16[DIMN * DIMN]; // Wref rounded to fp16

// ---------------- helpers ----------------
__device__ __forceinline__ uint32_t smem_u32(const void* p) {
    return (uint32_t)__cvta_generic_to_shared(p);
}

__device__ __forceinline__ uint32_t swz(uint32_t o) {
    return o ^ ((o >> 3) & 0x70);
}

__device__ __forceinline__ uint32_t pack2h(__half a, __half b) {
    __half2 t(a, b);  // a at low half
    return *reinterpret_cast<uint32_t*>(&t);
}

__device__ __forceinline__ float tanha(float x) {
    float y;
    asm("tanh.approx.f32 %0, %1;" : "=f"(y) : "f"(x));
    return y;
}

__device__ __forceinline__ void ldsm4(uint32_t* r, uint32_t addr) {
    asm volatile("ldmatrix.sync.aligned.m8n8.x4.shared.b16 {%0,%1,%2,%3}, [%4];"
                 : "=r"(r[0]), "=r"(r[1]), "=r"(r[2]), "=r"(r[3])
                 : "r"(addr));
}

__device__ __forceinline__ void mma_f16(float* c, const uint32_t* a,
                                        uint32_t b0, uint32_t b1) {
    asm volatile(
        "mma.sync.aligned.m16n8k16.row.col.f32.f16.f16.f32 "
        "{%0,%1,%2,%3}, {%4,%5,%6,%7}, {%8,%9}, {%0,%1,%2,%3};"
        : "+f"(c[0]), "+f"(c[1]), "+f"(c[2]), "+f"(c[3])
        : "r"(a[0]), "r"(a[1]), "r"(a[2]), "r"(a[3]), "r"(b0), "r"(b1));
}

__device__ __forceinline__ void cp_async16(uint32_t dst, const void* src) {
    asm volatile("cp.async.cg.shared.global [%0], [%1], 16;"
                 :: "r"(dst), "l"(src) : "memory");
}

__device__ __forceinline__ void prefetch_l1(const void* p) {
    asm volatile("prefetch.global.L1 [%0];" :: "l"(p));
}

// ---------------- merged prep kernel ----------------
// Grid 96: CTAs 0..63 -> qq (4 b-rows each, 4x Wq reuse + 4-way ILP);
//          CTAs 64..95 -> W16 conversion (2048 elements each).
__global__ void prep_all(const float* __restrict__ query,
                         const float* __restrict__ Wq,
                         const float* __restrict__ bq,
                         const float* __restrict__ bref,
                         const float* __restrict__ Wref) {
    const int tid = threadIdx.x;
    if (blockIdx.x >= 64) {
        int i = (blockIdx.x - 64) * 2048 + tid;
#pragma unroll
        for (int j = 0; j < 8; j++)
            g_W16[i + j * 256] = __float2half(Wref[i + j * 256]);
        return;
    }
    __shared__ __align__(16) float qrows[4 * DIMN];
    const int bq0 = blockIdx.x * 4;
#pragma unroll
    for (int r = 0; r < 4; r++)
        qrows[r * DIMN + tid] = query[(bq0 + r) * DIMN + tid];
    __syncthreads();
    const float4* w  = (const float4*)(Wq + (size_t)tid * DIMN);
    const float4* a0 = (const float4*)(qrows);
    const float4* a1 = (const float4*)(qrows + DIMN);
    const float4* a2 = (const float4*)(qrows + 2 * DIMN);
    const float4* a3 = (const float4*)(qrows + 3 * DIMN);
    float s0 = 0.f, s1 = 0.f, s2 = 0.f, s3 = 0.f;
#pragma unroll 8
    for (int e = 0; e < 64; e++) {
        float4 wv = w[e];
        float4 x0 = a0[e], x1 = a1[e], x2 = a2[e], x3 = a3[e];
        s0 = fmaf(wv.x, x0.x, fmaf(wv.y, x0.y, fmaf(wv.z, x0.z, fmaf(wv.w, x0.w, s0))));
        s1 = fmaf(wv.x, x1.x, fmaf(wv.y, x1.y, fmaf(wv.z, x1.z, fmaf(wv.w, x1.w, s1))));
        s2 = fmaf(wv.x, x2.x, fmaf(wv.y, x2.y, fmaf(wv.z, x2.z, fmaf(wv.w, x2.w, s2))));
        s3 = fmaf(wv.x, x3.x, fmaf(wv.y, x3.y, fmaf(wv.z, x3.z, fmaf(wv.w, x3.w, s3))));
    }
    const float bb = bq[tid] + bref[tid];
    g_qq[(bq0 + 0) * DIMN + tid] = s0 + bb;
    g_qq[(bq0 + 1) * DIMN + tid] = s1 + bb;
    g_qq[(bq0 + 2) * DIMN + tid] = s2 + bb;
    g_qq[(bq0 + 3) * DIMN + tid] = s3 + bb;
}

// ---------------- main kernel ----------------
// Grid (2048, 2): token k = blockIdx.x, b-half = blockIdx.y.
// SMEM (97KB -> 2 CTAs/SM):
//   A chunks 0..3 (fp16, write-once, whole K resident): c*16384, [0, 65536)
//   W stage p (p=0,1): 65536 + p*16384  (128 d-rows x 128B, fp16)
//   v: 98304 (1KB).  red reuses [0,1024) at the end.
#define SM_W   65536
#define SM_V   98304
#define SMEM_TOTAL 99328

__global__ void __launch_bounds__(256, 2) attn_main(const float* __restrict__ enc,
                                                    const float* __restrict__ vvec,
                                                    float* __restrict__ out) {
    extern __shared__ char smem[];
    const uint32_t sb = smem_u32(smem);
    const int tid = threadIdx.x;
    const int wid = tid >> 5;
    const int lane = tid & 31;
    const int wm = wid & 3;            // M block: rows wm*32 .. +32
    const int wn = wid >> 2;           // N half within pass: cols wn*64 .. +64
    const int k = blockIdx.x;
    const int b0 = blockIdx.y * 128;
    const int kb = k * BSZ + b0;

    float* v_s = (float*)(smem + SM_V);
    v_s[tid] = vvec[tid];

    // per-lane swizzled ldmatrix bases
    const uint32_t a0 = swz((uint32_t)((wm * 32 + (lane & 15)) * 128 + (lane >> 4) * 16));
    const uint32_t a1 = a0 + 2048;  // +16 rows (additive above swizzle bits)
    const uint32_t w_row = (uint32_t)((lane & 7) + ((lane & 16) ? 8 : 0));
    const uint32_t w0s = swz((uint32_t)((wn * 64 + w_row) * 128 + ((lane >> 3) & 1) * 16));

    // W stage issue: stage s; d-rows (s>>2)*128+[0,128), k-cols (s&3)*64+[0,64)
    auto issue_W = [&](int s) {
        uint32_t wst = sb + SM_W + (uint32_t)(s & 1) * 16384;
        const __half* src = g_W16 + ((s >> 2) * 128) * DIMN + (s & 3) * 64;
#pragma unroll
        for (int j = 0; j < 4; j++) {
            int gi = j * 256 + tid;           // 1024 granules of 16B
            int d = gi >> 3, seg = gi & 7;
            cp_async16(wst + swz((uint32_t)(d * 128 + seg * 16)),
                       src + d * DIMN + seg * 8);
        }
        asm volatile("cp.async.commit_group;" ::: "memory");
    };

    // accumulators: 2 m-tiles x 8 n8-tiles x 4 regs (one 128-col pass at a time)
    float acc[2][8][4];
#pragma unroll
    for (int mt = 0; mt < 2; mt++)
#pragma unroll
        for (int t = 0; t < 8; t++)
#pragma unroll
            for (int j = 0; j < 4; j++) acc[mt][t][j] = 0.0f;

    float u00 = 0.f, u01 = 0.f, u10 = 0.f, u11 = 0.f;

    // epilogue row indices / qq pointers (rows wm*32 + q + {0,8,16,24})
    const int q = lane >> 2;
    const int rbase = b0 + wm * 32 + q;
    const float* qp0 = g_qq + (size_t)rbase * DIMN;
    const float* qp1 = g_qq + (size_t)(rbase + 8) * DIMN;
    const float* qp2 = g_qq + (size_t)(rbase + 16) * DIMN;
    const float* qp3 = g_qq + (size_t)(rbase + 24) * DIMN;
    const int cbase = 2 * (lane & 3);

    // fold pieces for tiles t=2np, 2np+1 of pass pe (reads then zeroes acc)
    auto fold2 = [&](int pe, int np) {
#pragma unroll
        for (int t = 2 * np; t < 2 * np + 2; t++) {
            int cb = pe * 128 + wn * 64 + t * 8 + cbase;
            float2 vfrag = *(const float2*)(v_s + cb);
            float2 qa = *(const float2*)(qp0 + cb);
            float2 qb = *(const float2*)(qp1 + cb);
            float2 qc = *(const float2*)(qp2 + cb);
            float2 qd = *(const float2*)(qp3 + cb);
            u00 = fmaf(vfrag.x, tanha(acc[0][t][0] + qa.x), u00);
            u00 = fmaf(vfrag.y, tanha(acc[0][t][1] + qa.y), u00);
            u01 = fmaf(vfrag.x, tanha(acc[0][t][2] + qb.x), u01);
            u01 = fmaf(vfrag.y, tanha(acc[0][t][3] + qb.y), u01);
            u10 = fmaf(vfrag.x, tanha(acc[1][t][0] + qc.x), u10);
            u10 = fmaf(vfrag.y, tanha(acc[1][t][1] + qc.y), u10);
            u11 = fmaf(vfrag.x, tanha(acc[1][t][2] + qd.x), u11);
            u11 = fmaf(vfrag.y, tanha(acc[1][t][3] + qd.y), u11);
#pragma unroll
            for (int mt = 0; mt < 2; mt++)
#pragma unroll
                for (int j = 0; j < 4; j++) acc[mt][t][j] = 0.0f;
        }
    };

    issue_W(0);

    for (int s = 0; s < 8; s++) {
        const int c = s & 3;
        const int pe = s >> 2;
        const uint32_t abase = sb + (uint32_t)c * 16384;
        const uint32_t wbase = sb + SM_W + (uint32_t)(s & 1) * 16384;

        // prefetch qq lines for the pass epilogue (used at s+1 / end of s)
        if (c == 3) {
            const int cb0 = pe * 128 + wn * 64;
#pragma unroll
            for (int h = 0; h < 2; h++) {
                prefetch_l1(qp0 + cb0 + h * 32);
                prefetch_l1(qp1 + cb0 + h * 32);
                prefetch_l1(qp2 + cb0 + h * 32);
                prefetch_l1(qp3 + cb0 + h * 32);
            }
        }

        if (s < 4) {
            // issue A LDGs first; their latency overlaps wait+sync+issue_W
            float4 st[8];
#pragma unroll
            for (int j = 0; j < 8; j++) {
                int gi = j * 256 + tid;
                int m = gi >> 4, f4 = gi & 15;
                st[j] = *(const float4*)(enc + (size_t)(kb + m) * DIMN +
                                         c * 64 + f4 * 4);
            }
            asm volatile("cp.async.wait_group 0;" ::: "memory");
            __syncthreads();          // all warps past compute(s-1)
            if (s < 7) issue_W(s + 1);
            // convert + STS (first consumer of st: residual LDG latency only)
#pragma unroll
            for (int j = 0; j < 8; j++) {
                int gi = j * 256 + tid;
                int m = gi >> 4, f4 = gi & 15;
                __half h0 = __float2half(st[j].x), h1 = __float2half(st[j].y);
                __half h2 = __float2half(st[j].z), h3 = __float2half(st[j].w);
                uint32_t sw = swz((uint32_t)(m * 128 + f4 * 8));
                *(uint2*)(smem + (size_t)c * 16384 + sw) =
                    make_uint2(pack2h(h0, h1), pack2h(h2, h3));
            }
            __syncthreads();          // A16(c) visible for ldsm
        } else {
            asm volatile("cp.async.wait_group 0;" ::: "memory");
            __syncthreads();
            if (s < 7) issue_W(s + 1);
        }

        // ---- compute chunk: 4 kk x 4 np x 4 MMA ----
        if (s == 4) {
            // kk = 0 with the pass-0 fold interleaved between MMA groups.
            // fold2(0, np) reads acc tiles 2np,2np+1 BEFORE the np-th MMA
            // group overwrites them (in-warp program order).
            const uint32_t kx0 = 0;
            uint32_t aF0[4], aF1[4];
            ldsm4(aF0, abase + (a0 ^ kx0));
            ldsm4(aF1, abase + (a1 ^ kx0));
            const uint32_t wk0 = w0s ^ kx0;
#pragma unroll
            for (int np = 0; np < 4; np++) {
                fold2(0, np);
                uint32_t w[4];
                ldsm4(w, wbase + wk0 + np * 2048);
                mma_f16(acc[0][2 * np],     aF0, w[0], w[1]);
                mma_f16(acc[0][2 * np + 1], aF0, w[2], w[3]);
                mma_f16(acc[1][2 * np],     aF1, w[0], w[1]);
                mma_f16(acc[1][2 * np + 1], aF1, w[2], w[3]);
            }
#pragma unroll
            for (int kk = 1; kk < 4; kk++) {
                const uint32_t kx = (uint32_t)(kk * 32);
                uint32_t bF0[4], bF1[4];
                ldsm4(bF0, abase + (a0 ^ kx));
                ldsm4(bF1, abase + (a1 ^ kx));
                const uint32_t wk = w0s ^ kx;
#pragma unroll
                for (int np = 0; np < 4; np++) {
                    uint32_t w[4];
                    ldsm4(w, wbase + wk + np * 2048);
                    mma_f16(acc[0][2 * np],     bF0, w[0], w[1]);
                    mma_f16(acc[0][2 * np + 1], bF0, w[2], w[3]);
                    mma_f16(acc[1][2 * np],     bF1, w[0], w[1]);
                    mma_f16(acc[1][2 * np + 1], bF1, w[2], w[3]);
                }
            }
        } else {
#pragma unroll
            for (int kk = 0; kk < 4; kk++) {
                const uint32_t kx = (uint32_t)(kk * 32);
                uint32_t aF0[4], aF1[4];
                ldsm4(aF0, abase + (a0 ^ kx));
                ldsm4(aF1, abase + (a1 ^ kx));
                const uint32_t wk = w0s ^ kx;
#pragma unroll
                for (int np = 0; np < 4; np++) {
                    uint32_t w[4];
                    ldsm4(w, wbase + wk + np * 2048);
                    mma_f16(acc[0][2 * np],     aF0, w[0], w[1]);
                    mma_f16(acc[0][2 * np + 1], aF0, w[2], w[3]);
                    mma_f16(acc[1][2 * np],     aF1, w[0], w[1]);
                    mma_f16(acc[1][2 * np + 1], aF1, w[2], w[3]);
                }
            }
        }
    }

    // ---- final fold (pass 1) ----
#pragma unroll
    for (int np = 0; np < 4; np++) fold2(1, np);

    // reduce across the 4 lanes sharing each row
    u00 += __shfl_xor_sync(0xFFFFFFFF, u00, 1);
    u00 += __shfl_xor_sync(0xFFFFFFFF, u00, 2);
    u01 += __shfl_xor_sync(0xFFFFFFFF, u01, 1);
    u01 += __shfl_xor_sync(0xFFFFFFFF, u01, 2);
    u10 += __shfl_xor_sync(0xFFFFFFFF, u10, 1);
    u10 += __shfl_xor_sync(0xFFFFFFFF, u10, 2);
    u11 += __shfl_xor_sync(0xFFFFFFFF, u11, 1);
    u11 += __shfl_xor_sync(0xFFFFFFFF, u11, 2);

    // cross-warp (wn) reduction via smem (A chunks are dead now)
    __syncthreads();
    float* red = (float*)smem;  // [2][128]
    if ((lane & 3) == 0) {
        red[wn * 128 + wm * 32 + q] = u00;
        red[wn * 128 + wm * 32 + 8 + q] = u01;
        red[wn * 128 + wm * 32 + 16 + q] = u10;
        red[wn * 128 + wm * 32 + 24 + q] = u11;
    }
    __syncthreads();
    if (tid < 128) {
        float u = red[tid] + red[128 + tid];
        out[(size_t)(b0 + tid) * KTOK + k] = 10.0f * tanhf(u);
    }
}

// ---------------- launch ----------------
extern "C" void kernel_launch(void* const* d_in, const int* in_sizes, int n_in,
                              void* d_out, int out_size) {
    (void)in_sizes; (void)n_in; (void)out_size;
    const float* enc   = (const float*)d_in[0];
    const float* query = (const float*)d_in[1];
    const float* Wq    = (const float*)d_in[2];
    const float* bq    = (const float*)d_in[3];
    const float* Wref  = (const float*)d_in[4];
    const float* bref  = (const float*)d_in[5];
    const float* v     = (const float*)d_in[6];
    float* out = (float*)d_out;

    prep_all<<<96, 256>>>(query, Wq, bq, bref, Wref);

    cudaFuncSetAttribute(attn_main, cudaFuncAttributeMaxDynamicSharedMemorySize,
                         SMEM_TOTAL);
    dim3 grid(KTOK, 2);
    attn_main<<<grid, 256, SMEM_TOTAL>>>(enc, v, out);
}